// round 6
// baseline (speedup 1.0000x reference)
#include <cuda_runtime.h>

// Cost-volume construction:
//   out[0, c,      d, h, w] = imgl[0, c, h, w]                      (broadcast over d)
//   out[0, c + 32, d, h, w] = (w >= d) ? imgr[0, c, h, w - d] : 0
// Shapes: imgl/imgr (1, 32, 256, 480) f32, out (1, 64, 32, 256, 480) f32.
//
// R6: plane-sequential writer. One CTA per half (c,d)-plane; each CTA's
// write stream is strictly sequential (245KB, 4KB fully-coalesced waves,
// zero address jumps) to maximize DRAM page-hit runs. Right-half shift
// rebuilt from two ALIGNED float4 loads + compile-time element select
// (m = (-d) mod 4 uniform per block). Alignment => the w<d zero boundary
// never splits a float4; q=ceil(d/4)>=1 whenever hi is needed => no OOB.

constexpr int C  = 32;
constexpr int D  = 32;
constexpr int H2 = 256;
constexpr int W2 = 480;
constexpr int W4 = W2 / 4;               // 120
constexpr int PLANE  = H2 * W2;          // 122880 floats
constexpr int PLANE4 = PLANE / 4;        // 30720 float4
constexpr int HALVES = 2;
constexpr int CHUNK4 = PLANE4 / HALVES;  // 15360 float4 per CTA
constexpr int BLOCK  = 256;
constexpr int ITER   = CHUNK4 / BLOCK;   // 60

template <int M>
__device__ __forceinline__ void right_loop(
    const float4* __restrict__ rp,   // input plane (c-32), as float4
    float4* __restrict__ op,         // output plane (c,d), as float4
    int p0, int q)
{
#pragma unroll 4
    for (int i = 0; i < ITER; ++i) {
        int p  = p0 + i * BLOCK;
        int w4 = p % W4;
        int h  = p / W4;
        const float4* row = rp + h * W4;

        int lo4 = w4 - q;
        float4 lo = (lo4 >= 0) ? __ldg(row + lo4) : make_float4(0.f, 0.f, 0.f, 0.f);
        float4 v;
        if (M == 0) {
            v = lo;                       // d % 4 == 0: pure shifted copy
        } else {
            int hi4 = lo4 + 1;            // hi4 <= 119 guaranteed (q >= 1)
            float4 hi = (hi4 >= 0) ? __ldg(row + hi4) : make_float4(0.f, 0.f, 0.f, 0.f);
            v.x = (M == 1) ? lo.y : (M == 2) ? lo.z : lo.w;
            v.y = (M == 1) ? lo.z : (M == 2) ? lo.w : hi.x;
            v.z = (M == 1) ? lo.w : (M == 2) ? hi.x : hi.y;
            v.w = (M == 1) ? hi.x : (M == 2) ? hi.y : hi.z;
        }
        __stcs(op + p, v);
    }
}

__global__ __launch_bounds__(BLOCK) void cost_volume_kernel(
    const float* __restrict__ imgl,
    const float* __restrict__ imgr,
    float* __restrict__ out)
{
    int b    = blockIdx.x;               // 0..4095
    int half = b & 1;
    int d    = (b >> 1) & (D - 1);
    int c    = b >> 6;                   // 0..63

    int p0 = half * CHUNK4 + threadIdx.x;
    float4* op = reinterpret_cast<float4*>(out) + (c * D + d) * PLANE4;

    if (c < C) {
        // ---- Left half: sequential copy of imgl plane c ----
        const float4* lp = reinterpret_cast<const float4*>(imgl) + c * PLANE4;
#pragma unroll 4
        for (int i = 0; i < ITER; ++i) {
            int p = p0 + i * BLOCK;
            __stcs(op + p, __ldg(lp + p));
        }
    } else {
        // ---- Right half: d-shifted copy of imgr plane (c-32) ----
        const float4* rp = reinterpret_cast<const float4*>(imgr) + (c - C) * PLANE4;
        int m = (4 - (d & 3)) & 3;       // (w - d) mod 4, uniform per block
        int q = (d + 3) >> 2;            // ceil(d / 4)
        switch (m) {
            case 0: right_loop<0>(rp, op, p0, q); break;
            case 1: right_loop<1>(rp, op, p0, q); break;
            case 2: right_loop<2>(rp, op, p0, q); break;
            default: right_loop<3>(rp, op, p0, q); break;
        }
    }
}

extern "C" void kernel_launch(void* const* d_in, const int* in_sizes, int n_in,
                              void* d_out, int out_size)
{
    const float* imgl = (const float*)d_in[0];
    const float* imgr = (const float*)d_in[1];
    float* out = (float*)d_out;

    const int grid = 2 * C * D * HALVES; // 4096 CTAs
    cost_volume_kernel<<<grid, BLOCK>>>(imgl, imgr, out);
}

// round 7
// speedup vs baseline: 1.0391x; 1.0391x over previous
#include <cuda_runtime.h>

// Cost-volume construction:
//   out[0, c,      d, h, w] = imgl[0, c, h, w]                      (broadcast over d)
//   out[0, c + 32, d, h, w] = (w >= d) ? imgr[0, c, h, w - d] : 0
// Shapes: imgl/imgr (1, 32, 256, 480) f32, out (1, 64, 32, 256, 480) f32.
//
// R7 = R5 (159.7us, DRAM 80.1% — best) with the sliding-window scalar loads
// replaced by 3 aligned float4 loads. s = 4*w4 - d0 is a multiple of 4
// (d0 in {0,8,16,24}), so the 8 disparity windows [s-i, s-i+3], i=0..7 are
// all covered by quads at s-8, s-4, s. Quad bases are 4-aligned => a quad is
// either fully >= 0 or fully < 0 => per-quad zero predication is exact.
// Loads/thread: 8 instr -> 4 instr; store stream unchanged.

constexpr int C  = 32;
constexpr int D  = 32;
constexpr int H2 = 256;
constexpr int W2 = 480;
constexpr int W4 = W2 / 4;              // 120 float4 per row
constexpr int PLANE = H2 * W2;          // 122880 floats
constexpr int CH    = D * PLANE;        // 3,932,160 floats per out-channel
constexpr int DSPLIT = 8;               // disparities per thread
constexpr int NSPLIT = D / DSPLIT;      // 4

__global__ __launch_bounds__(512, 4) void cost_volume_kernel(
    const float* __restrict__ imgl,
    const float* __restrict__ imgr,
    float* __restrict__ out)
{
    int idx = blockIdx.x * blockDim.x + threadIdx.x;

    int w4 = idx % W4;
    int t  = idx / W4;
    int h  = t % H2;
    t /= H2;
    int c     = t % C;
    int split = t / C;                  // 0..3
    int w  = w4 * 4;
    int d0 = split * DSPLIT;

    // ---- Left operand: one float4, broadcast over DSPLIT disparities ----
    const float4 l = *reinterpret_cast<const float4*>(imgl + c * PLANE + h * W2 + w);

    // ---- Right operand: 12-float register window from 3 aligned loads ----
    const float* rrow = imgr + c * PLANE + h * W2;
    int s = w - d0;                     // multiple of 4, s >= -24

    float arr[12];
    const float4 z = make_float4(0.f, 0.f, 0.f, 0.f);
    float4 qa = (s - 8 >= 0) ? *reinterpret_cast<const float4*>(rrow + s - 8) : z;
    float4 qb = (s - 4 >= 0) ? *reinterpret_cast<const float4*>(rrow + s - 4) : z;
    float4 qc = (s     >= 0) ? *reinterpret_cast<const float4*>(rrow + s)     : z;
    arr[0] = qa.x; arr[1] = qa.y; arr[2]  = qa.z; arr[3]  = qa.w;
    arr[4] = qb.x; arr[5] = qb.y; arr[6]  = qb.z; arr[7]  = qb.w;
    arr[8] = qc.x; arr[9] = qc.y; arr[10] = qc.z; arr[11] = qc.w;

    float* outL = out + c * CH       + d0 * PLANE + h * W2 + w;
    float* outR = out + (c + C) * CH + d0 * PLANE + h * W2 + w;

    // interleaved stores: both write streams active every iteration
#pragma unroll
    for (int i = 0; i < DSPLIT; ++i) {
        float4 r = make_float4(arr[8 - i], arr[9 - i], arr[10 - i], arr[11 - i]);
        __stcs(reinterpret_cast<float4*>(outL + i * PLANE), l);
        __stcs(reinterpret_cast<float4*>(outR + i * PLANE), r);
    }
}

extern "C" void kernel_launch(void* const* d_in, const int* in_sizes, int n_in,
                              void* d_out, int out_size)
{
    const float* imgl = (const float*)d_in[0];
    const float* imgr = (const float*)d_in[1];
    float* out = (float*)d_out;

    const int total = NSPLIT * C * H2 * W4;          // 3,932,160 threads
    const int block = 512;
    const int grid  = (total + block - 1) / block;   // 7680 blocks
    cost_volume_kernel<<<grid, block>>>(imgl, imgr, out);
}